// round 7
// baseline (speedup 1.0000x reference)
#include <cuda_runtime.h>
#include <cstdint>
#include <cfloat>

typedef unsigned long long ull;

// Problem constants
#define NB   128
#define NP   8732
#define NC   21
#define TOPK 200
#define NT   1024

// Select/sort config
#define BIN0  6016
#define NBIN  128
#define CHCAP 1024
#define CCAP  48
#define OCAP  200

// Global scratch (no allocation allowed)
__device__ float4 g_boxes[NB * NP];
__device__ ull    g_keys [NB * NP];

// key = [monotone score:32][~idx:16][cls:8][0:8]; unsigned MAX == (score desc, idx asc)
__device__ __forceinline__ ull pack_key(float v, unsigned idx, unsigned cls) {
    unsigned bq = __float_as_uint(v);
    bq ^= (unsigned)(((int)bq >> 31) | 0x80000000);
    return ((ull)bq << 32) | ((ull)((~idx) & 0xFFFFu) << 16) | ((ull)cls << 8);
}

// ===========================================================================
// Kernel 1: streaming softmax/argmax/decode. One warp per 32 flat rows.
// No block barriers; float4-staged conf loads; grid-balanced.
// ===========================================================================
#define K1_THREADS 256
#define K1_WPB     8
#define NGROUPS    ((NB * NP) / 32)          // 34928 exactly
#define K1_BLOCKS  (NGROUPS / K1_WPB)        // 4366

__global__ __launch_bounds__(K1_THREADS, 5)
void prep_kernel(const float* __restrict__ loc,
                 const float* __restrict__ conf,
                 const float* __restrict__ prior) {
    __shared__ float stage[K1_WPB][688];     // 672 used + pad
    const int wid  = threadIdx.x >> 5;
    const int lane = threadIdx.x & 31;
    int g = blockIdx.x * K1_WPB + wid;
    if (g >= NGROUPS) return;

    const int e0 = g * 32;
    const float* src = conf + (size_t)e0 * NC;   // 672 contiguous floats

    // staged load: 168 float4 per warp
#pragma unroll
    for (int q = 0; q < 6; q++) {
        int o4 = q * 32 + lane;
        if (o4 < 168)
            *(float4*)&stage[wid][o4 * 4] = ((const float4*)src)[o4];
    }
    __syncwarp();

    const int e = e0 + lane;
    float c[NC];
#pragma unroll
    for (int q = 0; q < NC; q++) c[q] = stage[wid][lane * NC + q];  // stride 21: conflict-free

    float m = c[0];
#pragma unroll
    for (int q = 1; q < NC; q++) m = fmaxf(m, c[q]);
    float sum = 0.0f;
#pragma unroll
    for (int q = 0; q < NC; q++) sum += expf(c[q] - m);
    float bm = c[1]; int bc = 1;
#pragma unroll
    for (int q = 2; q < NC; q++) {
        if (c[q] > bm) { bm = c[q]; bc = q; }
    }
    float score = expf(bm - m) / sum;
    float ms = (score > 0.01f) ? score : -1.0f;

    int p = e % NP;                          // prior index within batch
    float4 l  = ((const float4*)loc)[e];
    float4 pr = ((const float4*)prior)[p];
    float cx = pr.x + l.x * 0.1f * pr.z;
    float cy = pr.y + l.y * 0.1f * pr.w;
    float w  = pr.z * expf(l.z * 0.2f);
    float h  = pr.w * expf(l.w * 0.2f);

    g_boxes[e] = make_float4(cx - w * 0.5f, cy - h * 0.5f,
                             cx + w * 0.5f, cy + h * 0.5f);
    g_keys[e]  = pack_key(ms, (unsigned)p, (unsigned)(bc - 1));
}

// ===========================================================================
// Kernel 2: per-batch select (histogram threshold) + sort + greedy walk.
// ===========================================================================
// smem byte offsets
#define OFF_WHIST  0                         // int[32][128]  16384
#define OFF_GHIST  16384                     // int[128]        512
#define OFF_HIST2  16896                     // int[256]       1024
#define OFF_CHA    17920                     // ull[1024]      8192
#define OFF_CHB    26112                     // ull[1024]      8192
#define OFF_CLIST  34304                     // float4[960]   15360
#define OFF_OBOX   49664                     // float4[200]    3200
#define OFF_OCLS   52864                     // int[200]        800
#define OFF_PFBOX  53664                     // float4[1024]  16384  (16B aligned)
#define OFF_SKEY   70048                     // ull[8732]     69856
#define OFF_SC     139904                    // scalars
#define SMEM_BYTES (139904 + 256 + 16)

__global__ __launch_bounds__(NT, 1)
void select_kernel(float* __restrict__ out) {
    extern __shared__ unsigned char smem_raw[];
    ull*    skey   = (ull*)(smem_raw + OFF_SKEY);
    int*    sc     = (int*)(smem_raw + OFF_SC);
    int*    ccount = sc + 16;
    ull*    slimit = (ull*)(smem_raw + OFF_SC + 192);
    int*    ghist  = (int*)(smem_raw + OFF_GHIST);
    int*    hist2  = (int*)(smem_raw + OFF_HIST2);
    ull*    chA    = (ull*)(smem_raw + OFF_CHA);
    ull*    chB    = (ull*)(smem_raw + OFF_CHB);
    float4* clist  = (float4*)(smem_raw + OFF_CLIST);
    float4* obox   = (float4*)(smem_raw + OFF_OBOX);
    int*    ocls   = (int*)(smem_raw + OFF_OCLS);
    float4* pfbox  = (float4*)(smem_raw + OFF_PFBOX);

    const int b    = blockIdx.x;
    const int tid  = threadIdx.x;
    const int wid  = tid >> 5;
    const int lane = tid & 31;
    const size_t base = (size_t)b * NP;
    const unsigned full = 0xffffffffu;
    float* outb = out + (size_t)b * (TOPK * 6);

    // ---- load this batch's keys into smem ----
    for (int i = 0; i < 9; i++) {
        int p = tid + i * NT;
        if (p < NP) skey[p] = g_keys[base + p];
    }
    if (tid < 32) ccount[tid] = 0;
    if (tid == 0) { sc[1] = 0; sc[2] = 0; sc[4] = 0; *slimit = ~0ull; }
    __syncthreads();

    // ================ Refill rounds (normally 1) ================
    for (int round = 0; round < 32; round++) {
        ull limit = *slimit;
        int want = TOPK - sc[1] + 184;

        // ---- per-warp 128-bin histogram (match-aggregated) ----
        int* whist = (int*)(smem_raw + OFF_WHIST) + wid * NBIN;
        for (int q = lane; q < NBIN; q += 32) whist[q] = 0;
        __syncwarp();
        for (int i = 0; i < 9; i++) {
            int e = tid + i * NT;
            ull k = (e < NP) ? skey[e] : 0ull;
            int bin = (int)(k >> 51) - BIN0;
            bool val = (e < NP) && (k < limit) && (bin >= 0) && (bin < NBIN);
            int mbin = val ? bin : -1;
            unsigned mm = __match_any_sync(full, mbin);
            if (val && lane == (__ffs(mm) - 1)) whist[mbin] += __popc(mm);
        }
        __syncthreads();
        if (tid < NBIN) {
            int acc = 0;
            int* wh = (int*)(smem_raw + OFF_WHIST);
#pragma unroll
            for (int w = 0; w < 32; w++) acc += wh[w * NBIN + tid];
            ghist[tid] = acc;
        }
        __syncthreads();

        // ---- parallel suffix-scan threshold select (warp 0) ----
        if (wid == 0) {
            if (lane == 0) { sc[0] = 0; sc[3] = 0; sc[5] = 0; sc[6] = 0; sc[7] = 0; sc[9] = 0; }
            __syncwarp();
            int c0 = ghist[lane * 4], c1 = ghist[lane * 4 + 1];
            int c2 = ghist[lane * 4 + 2], c3 = ghist[lane * 4 + 3];
            int s = c0 + c1 + c2 + c3;
            int suf = s;
#pragma unroll
            for (int o = 1; o < 32; o <<= 1) {
                int tt = __shfl_down_sync(full, suf, o);
                if (lane + o < 32) suf += tt;
            }
            int total = __shfl_sync(full, suf, 0);
            int cum = suf - s;
            int T = -1, A = 0, S = 0;
            if (cum < want && cum + c3 >= want) { T = lane * 4 + 3; A = cum; S = cum + c3; }
            cum += c3;
            if (T < 0 && cum < want && cum + c2 >= want) { T = lane * 4 + 2; A = cum; S = cum + c2; }
            cum += c2;
            if (T < 0 && cum < want && cum + c1 >= want) { T = lane * 4 + 1; A = cum; S = cum + c1; }
            cum += c1;
            if (T < 0 && cum < want && cum + c0 >= want) { T = lane * 4;     A = cum; S = cum + c0; }
            if (T >= 0) { sc[0] = T; sc[3] = A; sc[5] = S; }
            if (lane == 0 && total < want) { sc[6] = 1; sc[0] = 0; sc[3] = 0; sc[5] = total; }
        }
        __syncthreads();

        // ---- optional 8-bit refinement if boundary bin is fat ----
        if (sc[5] > CHCAP && !sc[6]) {
            if (tid < 256) hist2[tid] = 0;
            __syncthreads();
            int Tc = BIN0 + sc[0];
            for (int i = 0; i < 9; i++) {
                int e = tid + i * NT;
                if (e < NP) {
                    ull k = skey[e];
                    if (k < limit && (int)(k >> 51) == Tc)
                        atomicAdd(&hist2[(int)((k >> 43) & 0xFF)], 1);
                }
            }
            __syncthreads();
            if (wid == 0) {
                int cc[8], s = 0;
#pragma unroll
                for (int q = 0; q < 8; q++) { cc[q] = hist2[lane * 8 + q]; s += cc[q]; }
                int suf = s;
#pragma unroll
                for (int o = 1; o < 32; o <<= 1) {
                    int tt = __shfl_down_sync(full, suf, o);
                    if (lane + o < 32) suf += tt;
                }
                int want2 = want - sc[3];
                int cum = suf - s;
                int T2 = -1;
#pragma unroll
                for (int q = 7; q >= 0; q--) {
                    if (T2 < 0 && cum < want2 && cum + cc[q] >= want2) T2 = lane * 8 + q;
                    cum += cc[q];
                }
                if (T2 >= 0) { sc[8] = T2; sc[9] = 1; }
            }
            __syncthreads();
        }
        ull thk = ((ull)(BIN0 + sc[0]) << 51);
        if (sc[9]) thk |= ((ull)sc[8] << 43);

        // ---- warp-aggregated gather ----
        for (int i = 0; i < 9; i++) {
            int e = tid + i * NT;
            ull k = (e < NP) ? skey[e] : 0ull;
            bool cnd = (k >= thk) && (k < limit);
            unsigned mm = __ballot_sync(full, cnd);
            int cnt = __popc(mm);
            int bp = 0;
            if (lane == 0 && cnt) bp = atomicAdd(&sc[7], cnt);
            bp = __shfl_sync(full, bp, 0);
            if (cnd) {
                int pos = bp + __popc(mm & ((1u << lane) - 1u));
                if (pos < CHCAP) chA[pos] = k;
            }
        }
        __syncthreads();
        int Sg = sc[7]; if (Sg > CHCAP) Sg = CHCAP;

        // ---- dynamic-width hybrid bitonic sort (descending) ----
        int P2 = 64; while (P2 < Sg) P2 <<= 1;
        for (int q = Sg + tid; q < P2; q += NT) chA[q] = 0ull;
        __syncthreads();
        {
            ull v = (tid < P2) ? chA[tid] : 0ull;
            ull* bufs[2] = { chA, chB };
            int pb = 0;
            for (int k = 2; k <= P2; k <<= 1) {
                int j = k >> 1;
                for (; j >= 32; j >>= 1) {         // cross-warp: ping-pong
                    if (tid < P2) bufs[pb][tid] = v;
                    __syncthreads();
                    if (tid < P2) {
                        ull o = bufs[pb][tid ^ j];
                        bool keepmax = ((tid & k) == 0) == ((tid & j) == 0);
                        bool gt = v > o;
                        v = keepmax ? (gt ? v : o) : (gt ? o : v);
                    }
                    pb ^= 1;
                }
                for (; j > 0; j >>= 1) {           // in-warp: shfl
                    ull o = __shfl_xor_sync(full, v, j);
                    bool keepmax = ((tid & k) == 0) == ((tid & j) == 0);
                    bool gt = v > o;
                    v = keepmax ? (gt ? v : o) : (gt ? o : v);
                }
            }
            if (tid < P2) chA[tid] = v;
        }
        __syncthreads();

        // ---- parallel prefetch of candidate boxes ----
        if (tid < Sg) {
            ull k = chA[tid];
            int idx = (int)((~(unsigned)(k >> 16)) & 0xFFFFu);
            pfbox[tid] = g_boxes[base + idx];
        }
        __syncthreads();

        // ---- window-parallel greedy walk (warp 0) ----
        if (wid == 0) {
            int nout = sc[1];
            int done = 0;
            for (int w0 = 0; w0 < Sg && nout < TOPK && !done; w0 += 32) {
                int m = Sg - w0; if (m > 32) m = 32;
                ull k = (lane < m) ? chA[w0 + lane] : 0ull;
                unsigned hb = (unsigned)(k >> 32);
                bool valid = hb > 0x80000000u;
                unsigned validmask = __ballot_sync(full, valid);
                float4 cb = make_float4(0.f, 0.f, 0.f, 0.f);
                int cr = -1; float car = 0.f;
                if (valid) {
                    cr  = (int)((k >> 8) & 0xFFu);
                    cb  = pfbox[w0 + lane];
                    car = (cb.z - cb.x) * (cb.w - cb.y);
                }
                // vs previously-accepted (per-class + overflow lists)
                bool hit = false;
                if (valid) {
                    int nc = ccount[cr]; if (nc > CCAP) nc = CCAP;
                    for (int q = 0; q < nc; q++) {
                        float4 ab = clist[cr * CCAP + q];
                        float ix1 = fmaxf(ab.x, cb.x), iy1 = fmaxf(ab.y, cb.y);
                        float ix2 = fminf(ab.z, cb.z), iy2 = fminf(ab.w, cb.w);
                        float inter = fmaxf(ix2 - ix1, 0.f) * fmaxf(iy2 - iy1, 0.f);
                        float ar = (ab.z - ab.x) * (ab.w - ab.y);
                        if (inter / (ar + car - inter) > 0.45f) hit = true;
                    }
                    int oc = sc[4]; if (oc > OCAP) oc = OCAP;
                    for (int q = 0; q < oc; q++) {
                        if (ocls[q] == cr) {
                            float4 ab = obox[q];
                            float ix1 = fmaxf(ab.x, cb.x), iy1 = fmaxf(ab.y, cb.y);
                            float ix2 = fminf(ab.z, cb.z), iy2 = fminf(ab.w, cb.w);
                            float inter = fmaxf(ix2 - ix1, 0.f) * fmaxf(iy2 - iy1, 0.f);
                            float ar = (ab.z - ab.x) * (ab.w - ab.y);
                            if (inter / (ar + car - inter) > 0.45f) hit = true;
                        }
                    }
                }
                unsigned priormask = __ballot_sync(full, hit);
                // pairwise within window: uniform LDS box + shfl class
                unsigned supmask = 0;
                for (int rr = 0; rr < m; rr++) {
                    float4 rb = pfbox[w0 + rr];            // uniform broadcast
                    int    rc = __shfl_sync(full, cr, rr);
                    if (valid && rr < lane && rc == cr && ((validmask >> rr) & 1u)) {
                        float ix1 = fmaxf(rb.x, cb.x), iy1 = fmaxf(rb.y, cb.y);
                        float ix2 = fminf(rb.z, cb.z), iy2 = fminf(rb.w, cb.w);
                        float inter = fmaxf(ix2 - ix1, 0.f) * fmaxf(iy2 - iy1, 0.f);
                        float ra = (rb.z - rb.x) * (rb.w - rb.y);
                        if (inter / (ra + car - inter) > 0.45f) supmask |= 1u << rr;
                    }
                }
                // serial resolve (uniform across lanes)
                unsigned accept = 0;
                for (int rr = 0; rr < 32; rr++) {
                    unsigned srr = __shfl_sync(full, supmask, rr);
                    unsigned bit = 1u << rr;
                    if ((validmask & bit) && !(priormask & bit) && !(srr & accept))
                        accept |= bit;
                }
                int rem = TOPK - nout;
                unsigned lmask = (1u << lane) - 1u;
                int rank = __popc(accept & lmask);
                if (((accept >> lane) & 1u) && rank < rem) {
                    int pos = nout + rank;
                    float* orow = outb + pos * 6;
                    orow[0] = cb.x; orow[1] = cb.y; orow[2] = cb.z; orow[3] = cb.w;
                    orow[4] = __uint_as_float(hb ^ 0x80000000u);
                    orow[5] = (float)cr;
                    int slot = atomicAdd(&ccount[cr], 1);
                    if (slot < CCAP) clist[cr * CCAP + slot] = cb;
                    else {
                        int os = atomicAdd(&sc[4], 1);
                        if (os < OCAP) { obox[os] = cb; ocls[os] = cr; }
                    }
                }
                __syncwarp();
                int na = __popc(accept); if (na > rem) na = rem;
                nout += na;
                unsigned expect = (m == 32) ? 0xFFFFFFFFu : ((1u << m) - 1u);
                if (validmask != expect) done = 1;
            }
            if (lane == 0) { sc[1] = nout; sc[2] = done; }
        }
        __syncthreads();

        if (sc[1] >= TOPK || sc[2] || sc[6] || Sg == 0) break;
        if (tid == 0) *slimit = thk;
        __syncthreads();
    }

    // ================ zero-fill remaining rows ================
    int nout = sc[1];
    for (int q = nout * 6 + tid; q < TOPK * 6; q += NT) outb[q] = 0.0f;
}

// ---------------------------------------------------------------------------
extern "C" void kernel_launch(void* const* d_in, const int* in_sizes, int n_in,
                              void* d_out, int out_size) {
    const float* loc   = (const float*)d_in[0];
    const float* conf  = (const float*)d_in[1];
    const float* prior = (const float*)d_in[2];
    float* out = (float*)d_out;

    cudaFuncSetAttribute(select_kernel,
                         cudaFuncAttributeMaxDynamicSharedMemorySize,
                         SMEM_BYTES);

    prep_kernel<<<K1_BLOCKS, K1_THREADS>>>(loc, conf, prior);
    select_kernel<<<NB, NT, SMEM_BYTES>>>(out);
}

// round 8
// speedup vs baseline: 1.7787x; 1.7787x over previous
#include <cuda_runtime.h>
#include <cstdint>
#include <cfloat>

typedef unsigned long long ull;

// Problem constants
#define NB   128
#define NP   8732
#define NC   21
#define TOPK 200
#define NT   1024

// Select config
#define BIN0  6016
#define NBIN  128
#define CHCAP 1024
#define WANT  768
#define CCAP  200

// Global scratch (no allocation allowed)
__device__ float4 g_boxes[NB * NP];
__device__ ull    g_keys [NB * NP];

// key = [monotone score:32][~idx:16][cls:8][0:8]; unsigned MAX == (score desc, idx asc)
__device__ __forceinline__ ull pack_key(float v, unsigned idx, unsigned cls) {
    unsigned bq = __float_as_uint(v);
    bq ^= (unsigned)(((int)bq >> 31) | 0x80000000);
    return ((ull)bq << 32) | ((ull)((~idx) & 0xFFFFu) << 16) | ((ull)cls << 8);
}

// ===========================================================================
// Kernel 1: streaming softmax/argmax/decode. One warp per 32 flat rows.
// ===========================================================================
#define K1_THREADS 256
#define K1_WPB     8
#define NGROUPS    ((NB * NP) / 32)          // 34928 exactly
#define K1_BLOCKS  (NGROUPS / K1_WPB)        // 4366

__global__ __launch_bounds__(K1_THREADS, 5)
void prep_kernel(const float* __restrict__ loc,
                 const float* __restrict__ conf,
                 const float* __restrict__ prior) {
    __shared__ float stage[K1_WPB][688];
    const int wid  = threadIdx.x >> 5;
    const int lane = threadIdx.x & 31;
    int g = blockIdx.x * K1_WPB + wid;
    if (g >= NGROUPS) return;

    const int e0 = g * 32;
    const float* src = conf + (size_t)e0 * NC;

#pragma unroll
    for (int q = 0; q < 6; q++) {
        int o4 = q * 32 + lane;
        if (o4 < 168)
            *(float4*)&stage[wid][o4 * 4] = ((const float4*)src)[o4];
    }
    __syncwarp();

    const int e = e0 + lane;
    float c[NC];
#pragma unroll
    for (int q = 0; q < NC; q++) c[q] = stage[wid][lane * NC + q];

    float m = c[0];
#pragma unroll
    for (int q = 1; q < NC; q++) m = fmaxf(m, c[q]);
    float sum = 0.0f;
#pragma unroll
    for (int q = 0; q < NC; q++) sum += expf(c[q] - m);
    float bm = c[1]; int bc = 1;
#pragma unroll
    for (int q = 2; q < NC; q++) {
        if (c[q] > bm) { bm = c[q]; bc = q; }
    }
    float score = expf(bm - m) / sum;
    float ms = (score > 0.01f) ? score : -1.0f;

    int p = e % NP;
    float4 l  = ((const float4*)loc)[e];
    float4 pr = ((const float4*)prior)[p];
    float cx = pr.x + l.x * 0.1f * pr.z;
    float cy = pr.y + l.y * 0.1f * pr.w;
    float w  = pr.z * expf(l.z * 0.2f);
    float h  = pr.w * expf(l.w * 0.2f);

    g_boxes[e] = make_float4(cx - w * 0.5f, cy - h * 0.5f,
                             cx + w * 0.5f, cy + h * 0.5f);
    g_keys[e]  = pack_key(ms, (unsigned)p, (unsigned)(bc - 1));
}

// ===========================================================================
// Kernel 2: per-batch top-768 select + sort + 20 parallel per-class NMS walks
// + ordered compaction emit.
// ===========================================================================
// smem byte offsets
#define OFF_WHIST  0                         // int[32][128]   16384
#define OFF_GHIST  16384                     // int[128]         512
#define OFF_HIST2  16896                     // int[256]        1024
#define OFF_CHA    17920                     // ull[1024]       8192
#define OFF_CHB    26112                     // ull[1024]       8192
#define OFF_PFBOX  34304                     // float4[1024]   16384
#define OFF_CLIST  50688                     // float4[20*200] 64000
#define OFF_ACCF   114688                    // uchar[1024]     1024
#define OFF_WCNT   115712                    // int[32]          128
#define OFF_WBASE  115840                    // int[32]          128
#define OFF_SC     115968                    // int[64]          256
#define OFF_SKEY   116224                    // ull[8732]      69856
#define SMEM_BYTES (116224 + 69856 + 16)

__global__ __launch_bounds__(NT, 1)
void select_kernel(float* __restrict__ out) {
    extern __shared__ unsigned char smem_raw[];
    int*           ghist  = (int*)(smem_raw + OFF_GHIST);
    int*           hist2  = (int*)(smem_raw + OFF_HIST2);
    ull*           chA    = (ull*)(smem_raw + OFF_CHA);
    ull*           chB    = (ull*)(smem_raw + OFF_CHB);
    float4*        pfbox  = (float4*)(smem_raw + OFF_PFBOX);
    float4*        clist  = (float4*)(smem_raw + OFF_CLIST);
    unsigned char* accf   = (unsigned char*)(smem_raw + OFF_ACCF);
    int*           wcnt   = (int*)(smem_raw + OFF_WCNT);
    int*           wbase  = (int*)(smem_raw + OFF_WBASE);
    int*           sc     = (int*)(smem_raw + OFF_SC);
    int*           ccount = sc + 16;                         // 20 used
    ull*           slimit = (ull*)(sc + 48);
    ull*           skey   = (ull*)(smem_raw + OFF_SKEY);

    const int b    = blockIdx.x;
    const int tid  = threadIdx.x;
    const int wid  = tid >> 5;
    const int lane = tid & 31;
    const size_t base = (size_t)b * NP;
    const unsigned full = 0xffffffffu;
    float* outb = out + (size_t)b * (TOPK * 6);

    for (int i = 0; i < 9; i++) {
        int p = tid + i * NT;
        if (p < NP) skey[p] = g_keys[base + p];
    }
    if (tid < 20) ccount[tid] = 0;
    if (tid == 0) { sc[1] = 0; *slimit = ~0ull; }
    __syncthreads();

    // ================ Rounds (normally 1) ================
    for (int round = 0; round < 16; round++) {
        ull limit = *slimit;

        // ---- per-warp 128-bin histogram (match-aggregated) ----
        int* whist = (int*)(smem_raw + OFF_WHIST) + wid * NBIN;
        for (int q = lane; q < NBIN; q += 32) whist[q] = 0;
        __syncwarp();
        for (int i = 0; i < 9; i++) {
            int e = tid + i * NT;
            ull k = (e < NP) ? skey[e] : 0ull;
            int bin = (int)(k >> 51) - BIN0;
            bool val = (e < NP) && (k < limit) && (bin >= 0) && (bin < NBIN);
            int mbin = val ? bin : -1;
            unsigned mm = __match_any_sync(full, mbin);
            if (val && lane == (__ffs(mm) - 1)) whist[mbin] += __popc(mm);
        }
        __syncthreads();
        if (tid < NBIN) {
            int acc = 0;
            int* wh = (int*)(smem_raw + OFF_WHIST);
#pragma unroll
            for (int w = 0; w < 32; w++) acc += wh[w * NBIN + tid];
            ghist[tid] = acc;
        }
        __syncthreads();

        // ---- suffix-scan threshold select (warp 0) ----
        if (wid == 0) {
            if (lane == 0) { sc[0] = 0; sc[3] = 0; sc[5] = 0; sc[6] = 0; sc[7] = 0; sc[9] = 0; }
            __syncwarp();
            int c0 = ghist[lane * 4], c1 = ghist[lane * 4 + 1];
            int c2 = ghist[lane * 4 + 2], c3 = ghist[lane * 4 + 3];
            int s = c0 + c1 + c2 + c3;
            int suf = s;
#pragma unroll
            for (int o = 1; o < 32; o <<= 1) {
                int tt = __shfl_down_sync(full, suf, o);
                if (lane + o < 32) suf += tt;
            }
            int total = __shfl_sync(full, suf, 0);
            int cum = suf - s;
            int T = -1, A = 0, S = 0;
            if (cum < WANT && cum + c3 >= WANT) { T = lane * 4 + 3; A = cum; S = cum + c3; }
            cum += c3;
            if (T < 0 && cum < WANT && cum + c2 >= WANT) { T = lane * 4 + 2; A = cum; S = cum + c2; }
            cum += c2;
            if (T < 0 && cum < WANT && cum + c1 >= WANT) { T = lane * 4 + 1; A = cum; S = cum + c1; }
            cum += c1;
            if (T < 0 && cum < WANT && cum + c0 >= WANT) { T = lane * 4;     A = cum; S = cum + c0; }
            if (T >= 0) { sc[0] = T; sc[3] = A; sc[5] = S; }
            if (lane == 0 && total < WANT) { sc[6] = 1; sc[0] = 0; sc[3] = 0; sc[5] = total; }
        }
        __syncthreads();

        // ---- 8-bit refinement if boundary bin overflows chunk capacity ----
        if (sc[5] > CHCAP && !sc[6]) {
            if (tid < 256) hist2[tid] = 0;
            __syncthreads();
            int Tc = BIN0 + sc[0];
            for (int i = 0; i < 9; i++) {
                int e = tid + i * NT;
                if (e < NP) {
                    ull k = skey[e];
                    if (k < limit && (int)(k >> 51) == Tc)
                        atomicAdd(&hist2[(int)((k >> 43) & 0xFF)], 1);
                }
            }
            __syncthreads();
            if (wid == 0) {
                int cc[8], s = 0;
#pragma unroll
                for (int q = 0; q < 8; q++) { cc[q] = hist2[lane * 8 + q]; s += cc[q]; }
                int suf = s;
#pragma unroll
                for (int o = 1; o < 32; o <<= 1) {
                    int tt = __shfl_down_sync(full, suf, o);
                    if (lane + o < 32) suf += tt;
                }
                int want2 = WANT - sc[3];
                int cum = suf - s;
                int T2 = -1;
#pragma unroll
                for (int q = 7; q >= 0; q--) {
                    if (T2 < 0 && cum < want2 && cum + cc[q] >= want2) T2 = lane * 8 + q;
                    cum += cc[q];
                }
                if (T2 >= 0) { sc[8] = T2; sc[9] = 1; }
            }
            __syncthreads();
        }
        ull thk = ((ull)(BIN0 + sc[0]) << 51);
        if (sc[9]) thk |= ((ull)sc[8] << 43);

        // ---- warp-aggregated gather ----
        for (int i = 0; i < 9; i++) {
            int e = tid + i * NT;
            ull k = (e < NP) ? skey[e] : 0ull;
            bool cnd = (k >= thk) && (k < limit);
            unsigned mm = __ballot_sync(full, cnd);
            int cnt = __popc(mm);
            int bp = 0;
            if (lane == 0 && cnt) bp = atomicAdd(&sc[7], cnt);
            bp = __shfl_sync(full, bp, 0);
            if (cnd) {
                int pos = bp + __popc(mm & ((1u << lane) - 1u));
                if (pos < CHCAP) chA[pos] = k;
            }
        }
        __syncthreads();
        int Sg = sc[7]; if (Sg > CHCAP) Sg = CHCAP;
        if (Sg == 0) break;

        // ---- dynamic-width hybrid bitonic sort (descending) ----
        int P2 = 64; while (P2 < Sg) P2 <<= 1;
        for (int q = Sg + tid; q < P2; q += NT) chA[q] = 0ull;
        __syncthreads();
        {
            ull v = (tid < P2) ? chA[tid] : 0ull;
            ull* bufs[2] = { chA, chB };
            int pb = 0;
            for (int k = 2; k <= P2; k <<= 1) {
                int j = k >> 1;
                for (; j >= 32; j >>= 1) {
                    if (tid < P2) bufs[pb][tid] = v;
                    __syncthreads();
                    if (tid < P2) {
                        ull o = bufs[pb][tid ^ j];
                        bool keepmax = ((tid & k) == 0) == ((tid & j) == 0);
                        bool gt = v > o;
                        v = keepmax ? (gt ? v : o) : (gt ? o : v);
                    }
                    pb ^= 1;
                    __syncthreads();
                }
                for (; j > 0; j >>= 1) {
                    ull o = __shfl_xor_sync(full, v, j);
                    bool keepmax = ((tid & k) == 0) == ((tid & j) == 0);
                    bool gt = v > o;
                    v = keepmax ? (gt ? v : o) : (gt ? o : v);
                }
            }
            if (tid < P2) chA[tid] = v;
        }
        __syncthreads();

        // ---- parallel box prefetch + flag clear ----
        if (tid < Sg) {
            ull k = chA[tid];
            int idx = (int)((~(unsigned)(k >> 16)) & 0xFFFFu);
            pfbox[tid] = g_boxes[base + idx];
        }
        accf[tid] = 0;
        __syncthreads();

        // ---- 20 parallel per-class greedy NMS walks ----
        if (wid < 20) {
            int ncR = ccount[wid];
            for (int r0 = 0; r0 < Sg; r0 += 32) {
                int rem = Sg - r0;
                ull k = (lane < rem) ? chA[r0 + lane] : 0ull;
                bool mine = (lane < rem) && (((int)(k >> 8) & 0xFF) == wid);
                unsigned mask = __ballot_sync(full, mine);
                while (mask) {
                    int r = r0 + (__ffs(mask) - 1);
                    mask &= mask - 1;
                    float4 cb = pfbox[r];                 // uniform LDS.128
                    float car = (cb.z - cb.x) * (cb.w - cb.y);
                    bool hit = false;
                    for (int q0 = 0; q0 < ncR; q0 += 32) {
                        int q = q0 + lane;
                        if (q < ncR) {
                            float4 ab = clist[wid * CCAP + q];
                            float ix1 = fmaxf(ab.x, cb.x), iy1 = fmaxf(ab.y, cb.y);
                            float ix2 = fminf(ab.z, cb.z), iy2 = fminf(ab.w, cb.w);
                            float inter = fmaxf(ix2 - ix1, 0.f) * fmaxf(iy2 - iy1, 0.f);
                            float ar = (ab.z - ab.x) * (ab.w - ab.y);
                            if (inter / (ar + car - inter) > 0.45f) hit = true;
                        }
                    }
                    if (!__any_sync(full, hit)) {
                        if (ncR < CCAP) {               // >=CCAP: provably un-emittable
                            if (lane == 0) { clist[wid * CCAP + ncR] = cb; accf[r] = 1; }
                            ncR++;
                        }
                    }
                }
            }
            if (lane == 0) ccount[wid] = ncR;
        }
        __syncthreads();

        // ---- ordered compaction + emit ----
        bool f = (tid < Sg) && accf[tid];
        unsigned bal = __ballot_sync(full, f);
        if (lane == 0) wcnt[wid] = __popc(bal);
        __syncthreads();
        if (wid == 0) {
            int v = wcnt[lane];
            int x = v;
#pragma unroll
            for (int o = 1; o < 32; o <<= 1) {
                int t2 = __shfl_up_sync(full, x, o);
                if (lane >= o) x += t2;
            }
            wbase[lane] = x - v;
            if (lane == 31) sc[10] = x;   // total accepted this round
        }
        __syncthreads();
        int nout = sc[1];
        if (f) {
            int pos = nout + wbase[wid] + __popc(bal & ((1u << lane) - 1u));
            if (pos < TOPK) {
                ull k = chA[tid];
                float4 cb = pfbox[tid];
                float* orow = outb + pos * 6;
                orow[0] = cb.x; orow[1] = cb.y; orow[2] = cb.z; orow[3] = cb.w;
                orow[4] = __uint_as_float(((unsigned)(k >> 32)) ^ 0x80000000u);
                orow[5] = (float)((int)(k >> 8) & 0xFF);
            }
        }
        __syncthreads();
        if (tid == 0) {
            int nn = nout + sc[10];
            sc[1] = (nn > TOPK) ? TOPK : nn;
            *slimit = thk;
            sc[7] = 0;        // reset gather counter for next round
            sc[11] = sc[6];   // took-everything flag
        }
        __syncthreads();
        if (sc[1] >= TOPK || sc[11]) break;
    }

    // ================ zero-fill remaining rows ================
    int nout = sc[1];
    for (int q = nout * 6 + tid; q < TOPK * 6; q += NT) outb[q] = 0.0f;
}

// ---------------------------------------------------------------------------
extern "C" void kernel_launch(void* const* d_in, const int* in_sizes, int n_in,
                              void* d_out, int out_size) {
    const float* loc   = (const float*)d_in[0];
    const float* conf  = (const float*)d_in[1];
    const float* prior = (const float*)d_in[2];
    float* out = (float*)d_out;

    cudaFuncSetAttribute(select_kernel,
                         cudaFuncAttributeMaxDynamicSharedMemorySize,
                         SMEM_BYTES);

    prep_kernel<<<K1_BLOCKS, K1_THREADS>>>(loc, conf, prior);
    select_kernel<<<NB, NT, SMEM_BYTES>>>(out);
}

// round 9
// speedup vs baseline: 2.1824x; 1.2269x over previous
#include <cuda_runtime.h>
#include <cstdint>
#include <cfloat>

typedef unsigned long long ull;

// Problem constants
#define NB   128
#define NP   8732
#define NC   21
#define TOPK 200
#define NT   1024

// Select config
#define BIN0  6016
#define NBIN  128
#define CHCAP 1024
#define WANT  512
#define CCAP  200

// Global scratch (no allocation allowed). g_hist: written by prep (atomics),
// read+zeroed by select every launch -> zero at the start of every replay.
__device__ float4 g_boxes[NB * NP];
__device__ ull    g_keys [NB * NP];
__device__ int    g_hist [NB * NBIN];

// key = [monotone score:32][~idx:16][cls:8][0:8]; unsigned MAX == (score desc, idx asc)
__device__ __forceinline__ ull pack_key(float v, unsigned idx, unsigned cls) {
    unsigned bq = __float_as_uint(v);
    bq ^= (unsigned)(((int)bq >> 31) | 0x80000000);
    return ((ull)bq << 32) | ((ull)((~idx) & 0xFFFFu) << 16) | ((ull)cls << 8);
}

// ===========================================================================
// Kernel 1: streaming softmax/argmax/decode + fused per-batch histogram.
// ===========================================================================
#define K1_THREADS 256
#define K1_WPB     8
#define NGROUPS    ((NB * NP) / 32)          // 34928 exactly
#define K1_BLOCKS  (NGROUPS / K1_WPB)        // 4366

__global__ __launch_bounds__(K1_THREADS, 5)
void prep_kernel(const float* __restrict__ loc,
                 const float* __restrict__ conf,
                 const float* __restrict__ prior) {
    __shared__ float stage[K1_WPB][688];
    const int wid  = threadIdx.x >> 5;
    const int lane = threadIdx.x & 31;
    const unsigned full = 0xffffffffu;
    int g = blockIdx.x * K1_WPB + wid;
    if (g >= NGROUPS) return;

    const int e0 = g * 32;
    const float* src = conf + (size_t)e0 * NC;

#pragma unroll
    for (int q = 0; q < 6; q++) {
        int o4 = q * 32 + lane;
        if (o4 < 168)
            *(float4*)&stage[wid][o4 * 4] = ((const float4*)src)[o4];
    }
    __syncwarp();

    const int e = e0 + lane;
    float c[NC];
#pragma unroll
    for (int q = 0; q < NC; q++) c[q] = stage[wid][lane * NC + q];

    float m = c[0];
#pragma unroll
    for (int q = 1; q < NC; q++) m = fmaxf(m, c[q]);
    float sum = 0.0f;
#pragma unroll
    for (int q = 0; q < NC; q++) sum += expf(c[q] - m);
    float bm = c[1]; int bc = 1;
#pragma unroll
    for (int q = 2; q < NC; q++) {
        if (c[q] > bm) { bm = c[q]; bc = q; }
    }
    float score = expf(bm - m) / sum;
    float ms = (score > 0.01f) ? score : -1.0f;

    int bidx = e / NP;
    int p = e - bidx * NP;
    float4 l  = ((const float4*)loc)[e];
    float4 pr = ((const float4*)prior)[p];
    float cx = pr.x + l.x * 0.1f * pr.z;
    float cy = pr.y + l.y * 0.1f * pr.w;
    float w  = pr.z * expf(l.z * 0.2f);
    float h  = pr.w * expf(l.w * 0.2f);

    g_boxes[e] = make_float4(cx - w * 0.5f, cy - h * 0.5f,
                             cx + w * 0.5f, cy + h * 0.5f);
    ull key = pack_key(ms, (unsigned)p, (unsigned)(bc - 1));
    g_keys[e] = key;

    // fused per-batch histogram (match-aggregated global atomics)
    int bin = (int)(key >> 51) - BIN0;
    bool val = (bin >= 0) && (bin < NBIN);
    int slot = val ? (bidx * NBIN + bin) : -1;
    unsigned mm = __match_any_sync(full, slot);
    if (val && lane == (__ffs(mm) - 1)) atomicAdd(&g_hist[slot], __popc(mm));
}

// ===========================================================================
// Kernel 2: per-batch threshold (precomputed hist) + single gather pass +
// sort + 20 parallel per-class NMS walks + ordered compaction emit.
// ===========================================================================
// smem byte offsets
#define OFF_WHIST  0                         // int[32][128]   16384
#define OFF_GHIST  16384                     // int[128]         512
#define OFF_HIST2  16896                     // int[256]        1024
#define OFF_CHA    17920                     // ull[1024]       8192
#define OFF_CHB    26112                     // ull[1024]       8192
#define OFF_PFBOX  34304                     // float4[1024]   16384
#define OFF_CLIST  50688                     // float4[20*200] 64000
#define OFF_ACCF   114688                    // uchar[1024]     1024
#define OFF_WCNT   115712                    // int[32]          128
#define OFF_WBASE  115840                    // int[32]          128
#define OFF_SC     115968                    // int[64]          256
#define SMEM_BYTES (115968 + 256 + 16)

__global__ __launch_bounds__(NT, 1)
void select_kernel(float* __restrict__ out) {
    extern __shared__ unsigned char smem_raw[];
    int*           ghist  = (int*)(smem_raw + OFF_GHIST);
    int*           hist2  = (int*)(smem_raw + OFF_HIST2);
    ull*           chA    = (ull*)(smem_raw + OFF_CHA);
    ull*           chB    = (ull*)(smem_raw + OFF_CHB);
    float4*        pfbox  = (float4*)(smem_raw + OFF_PFBOX);
    float4*        clist  = (float4*)(smem_raw + OFF_CLIST);
    unsigned char* accf   = (unsigned char*)(smem_raw + OFF_ACCF);
    int*           wcnt   = (int*)(smem_raw + OFF_WCNT);
    int*           wbase  = (int*)(smem_raw + OFF_WBASE);
    int*           sc     = (int*)(smem_raw + OFF_SC);
    int*           ccount = sc + 16;                         // 20 used
    ull*           slimit = (ull*)(sc + 48);

    const int b    = blockIdx.x;
    const int tid  = threadIdx.x;
    const int wid  = tid >> 5;
    const int lane = tid & 31;
    const size_t base = (size_t)b * NP;
    const unsigned full = 0xffffffffu;
    float* outb = out + (size_t)b * (TOPK * 6);

    // read precomputed histogram, then zero it for the next replay
    if (tid < NBIN) {
        ghist[tid] = g_hist[b * NBIN + tid];
        g_hist[b * NBIN + tid] = 0;
    }
    if (tid < 20) ccount[tid] = 0;
    if (tid == 0) { sc[1] = 0; *slimit = ~0ull; }
    __syncthreads();

    // ================ Rounds (normally 1) ================
    for (int round = 0; round < 16; round++) {
        ull limit = *slimit;

        // rounds >= 1: rebuild histogram from g_keys with limit (rare)
        if (round > 0) {
            int* whist = (int*)(smem_raw + OFF_WHIST) + wid * NBIN;
            for (int q = lane; q < NBIN; q += 32) whist[q] = 0;
            __syncwarp();
            for (int i = 0; i < 9; i++) {
                int e = tid + i * NT;
                ull k = (e < NP) ? g_keys[base + e] : 0ull;
                int bin = (int)(k >> 51) - BIN0;
                bool val = (e < NP) && (k < limit) && (bin >= 0) && (bin < NBIN);
                int mbin = val ? bin : -1;
                unsigned mm = __match_any_sync(full, mbin);
                if (val && lane == (__ffs(mm) - 1)) whist[mbin] += __popc(mm);
            }
            __syncthreads();
            if (tid < NBIN) {
                int acc = 0;
                int* wh = (int*)(smem_raw + OFF_WHIST);
#pragma unroll
                for (int w = 0; w < 32; w++) acc += wh[w * NBIN + tid];
                ghist[tid] = acc;
            }
            __syncthreads();
        }

        // ---- suffix-scan threshold select (warp 0) ----
        if (wid == 0) {
            if (lane == 0) { sc[0] = 0; sc[3] = 0; sc[5] = 0; sc[6] = 0; sc[7] = 0; sc[9] = 0; }
            __syncwarp();
            int c0 = ghist[lane * 4], c1 = ghist[lane * 4 + 1];
            int c2 = ghist[lane * 4 + 2], c3 = ghist[lane * 4 + 3];
            int s = c0 + c1 + c2 + c3;
            int suf = s;
#pragma unroll
            for (int o = 1; o < 32; o <<= 1) {
                int tt = __shfl_down_sync(full, suf, o);
                if (lane + o < 32) suf += tt;
            }
            int total = __shfl_sync(full, suf, 0);
            int cum = suf - s;
            int T = -1, A = 0, S = 0;
            if (cum < WANT && cum + c3 >= WANT) { T = lane * 4 + 3; A = cum; S = cum + c3; }
            cum += c3;
            if (T < 0 && cum < WANT && cum + c2 >= WANT) { T = lane * 4 + 2; A = cum; S = cum + c2; }
            cum += c2;
            if (T < 0 && cum < WANT && cum + c1 >= WANT) { T = lane * 4 + 1; A = cum; S = cum + c1; }
            cum += c1;
            if (T < 0 && cum < WANT && cum + c0 >= WANT) { T = lane * 4;     A = cum; S = cum + c0; }
            if (T >= 0) { sc[0] = T; sc[3] = A; sc[5] = S; }
            if (lane == 0 && total < WANT) { sc[6] = 1; sc[0] = 0; sc[3] = 0; sc[5] = total; }
        }
        __syncthreads();

        // ---- 8-bit refinement if boundary bin overflows chunk capacity ----
        if (sc[5] > CHCAP && !sc[6]) {
            if (tid < 256) hist2[tid] = 0;
            __syncthreads();
            int Tc = BIN0 + sc[0];
            for (int i = 0; i < 9; i++) {
                int e = tid + i * NT;
                if (e < NP) {
                    ull k = g_keys[base + e];
                    if (k < limit && (int)(k >> 51) == Tc)
                        atomicAdd(&hist2[(int)((k >> 43) & 0xFF)], 1);
                }
            }
            __syncthreads();
            if (wid == 0) {
                int cc[8], s = 0;
#pragma unroll
                for (int q = 0; q < 8; q++) { cc[q] = hist2[lane * 8 + q]; s += cc[q]; }
                int suf = s;
#pragma unroll
                for (int o = 1; o < 32; o <<= 1) {
                    int tt = __shfl_down_sync(full, suf, o);
                    if (lane + o < 32) suf += tt;
                }
                int want2 = WANT - sc[3];
                int cum = suf - s;
                int T2 = -1;
#pragma unroll
                for (int q = 7; q >= 0; q--) {
                    if (T2 < 0 && cum < want2 && cum + cc[q] >= want2) T2 = lane * 8 + q;
                    cum += cc[q];
                }
                if (T2 >= 0) { sc[8] = T2; sc[9] = 1; }
            }
            __syncthreads();
        }
        ull thk = ((ull)(BIN0 + sc[0]) << 51);
        if (sc[9]) thk |= ((ull)sc[8] << 43);

        // ---- single gather pass over g_keys (MLP-batched loads) ----
        {
            ull kv[9];
#pragma unroll
            for (int i = 0; i < 9; i++) {
                int e = tid + i * NT;
                kv[i] = (e < NP) ? g_keys[base + e] : 0ull;
            }
#pragma unroll
            for (int i = 0; i < 9; i++) {
                bool cnd = (kv[i] >= thk) && (kv[i] < limit);
                unsigned mm = __ballot_sync(full, cnd);
                int cnt = __popc(mm);
                int bp = 0;
                if (lane == 0 && cnt) bp = atomicAdd(&sc[7], cnt);
                bp = __shfl_sync(full, bp, 0);
                if (cnd) {
                    int pos = bp + __popc(mm & ((1u << lane) - 1u));
                    if (pos < CHCAP) chA[pos] = kv[i];
                }
            }
        }
        __syncthreads();
        int Sg = sc[7]; if (Sg > CHCAP) Sg = CHCAP;
        if (Sg == 0) break;

        // ---- dynamic-width hybrid bitonic sort (descending) ----
        int P2 = 64; while (P2 < Sg) P2 <<= 1;
        for (int q = Sg + tid; q < P2; q += NT) chA[q] = 0ull;
        __syncthreads();
        {
            ull v = (tid < P2) ? chA[tid] : 0ull;
            ull* bufs[2] = { chA, chB };
            int pb = 0;
            for (int k = 2; k <= P2; k <<= 1) {
                int j = k >> 1;
                for (; j >= 32; j >>= 1) {
                    if (tid < P2) bufs[pb][tid] = v;
                    __syncthreads();
                    if (tid < P2) {
                        ull o = bufs[pb][tid ^ j];
                        bool keepmax = ((tid & k) == 0) == ((tid & j) == 0);
                        bool gt = v > o;
                        v = keepmax ? (gt ? v : o) : (gt ? o : v);
                    }
                    pb ^= 1;
                    __syncthreads();
                }
                for (; j > 0; j >>= 1) {
                    ull o = __shfl_xor_sync(full, v, j);
                    bool keepmax = ((tid & k) == 0) == ((tid & j) == 0);
                    bool gt = v > o;
                    v = keepmax ? (gt ? v : o) : (gt ? o : v);
                }
            }
            if (tid < P2) chA[tid] = v;
        }
        __syncthreads();

        // ---- parallel box prefetch + flag clear ----
        if (tid < Sg) {
            ull k = chA[tid];
            int idx = (int)((~(unsigned)(k >> 16)) & 0xFFFFu);
            pfbox[tid] = g_boxes[base + idx];
        }
        accf[tid] = 0;
        __syncthreads();

        // ---- 20 parallel per-class greedy NMS walks ----
        if (wid < 20) {
            int ncR = ccount[wid];
            for (int r0 = 0; r0 < Sg; r0 += 32) {
                int rem = Sg - r0;
                ull k = (lane < rem) ? chA[r0 + lane] : 0ull;
                bool mine = (lane < rem) && (((int)(k >> 8) & 0xFF) == wid);
                unsigned mask = __ballot_sync(full, mine);
                while (mask) {
                    int r = r0 + (__ffs(mask) - 1);
                    mask &= mask - 1;
                    float4 cb = pfbox[r];                 // uniform LDS.128
                    float car = (cb.z - cb.x) * (cb.w - cb.y);
                    bool hit = false;
                    for (int q0 = 0; q0 < ncR; q0 += 32) {
                        int q = q0 + lane;
                        if (q < ncR) {
                            float4 ab = clist[wid * CCAP + q];
                            float ix1 = fmaxf(ab.x, cb.x), iy1 = fmaxf(ab.y, cb.y);
                            float ix2 = fminf(ab.z, cb.z), iy2 = fminf(ab.w, cb.w);
                            float inter = fmaxf(ix2 - ix1, 0.f) * fmaxf(iy2 - iy1, 0.f);
                            float ar = (ab.z - ab.x) * (ab.w - ab.y);
                            if (inter / (ar + car - inter) > 0.45f) hit = true;
                        }
                    }
                    if (!__any_sync(full, hit)) {
                        if (ncR < CCAP) {               // >=CCAP: provably un-emittable
                            if (lane == 0) { clist[wid * CCAP + ncR] = cb; accf[r] = 1; }
                            ncR++;
                        }
                    }
                }
            }
            if (lane == 0) ccount[wid] = ncR;
        }
        __syncthreads();

        // ---- ordered compaction + emit ----
        bool f = (tid < Sg) && accf[tid];
        unsigned bal = __ballot_sync(full, f);
        if (lane == 0) wcnt[wid] = __popc(bal);
        __syncthreads();
        if (wid == 0) {
            int v = wcnt[lane];
            int x = v;
#pragma unroll
            for (int o = 1; o < 32; o <<= 1) {
                int t2 = __shfl_up_sync(full, x, o);
                if (lane >= o) x += t2;
            }
            wbase[lane] = x - v;
            if (lane == 31) sc[10] = x;   // total accepted this round
        }
        __syncthreads();
        int nout = sc[1];
        if (f) {
            int pos = nout + wbase[wid] + __popc(bal & ((1u << lane) - 1u));
            if (pos < TOPK) {
                ull k = chA[tid];
                float4 cb = pfbox[tid];
                float* orow = outb + pos * 6;
                orow[0] = cb.x; orow[1] = cb.y; orow[2] = cb.z; orow[3] = cb.w;
                orow[4] = __uint_as_float(((unsigned)(k >> 32)) ^ 0x80000000u);
                orow[5] = (float)((int)(k >> 8) & 0xFF);
            }
        }
        __syncthreads();
        if (tid == 0) {
            int nn = nout + sc[10];
            sc[1] = (nn > TOPK) ? TOPK : nn;
            *slimit = thk;
            sc[7] = 0;        // reset gather counter for next round
            sc[11] = sc[6];   // took-everything flag
        }
        __syncthreads();
        if (sc[1] >= TOPK || sc[11]) break;
    }

    // ================ zero-fill remaining rows ================
    int nout = sc[1];
    for (int q = nout * 6 + tid; q < TOPK * 6; q += NT) outb[q] = 0.0f;
}

// ---------------------------------------------------------------------------
extern "C" void kernel_launch(void* const* d_in, const int* in_sizes, int n_in,
                              void* d_out, int out_size) {
    const float* loc   = (const float*)d_in[0];
    const float* conf  = (const float*)d_in[1];
    const float* prior = (const float*)d_in[2];
    float* out = (float*)d_out;

    cudaFuncSetAttribute(select_kernel,
                         cudaFuncAttributeMaxDynamicSharedMemorySize,
                         SMEM_BYTES);

    prep_kernel<<<K1_BLOCKS, K1_THREADS>>>(loc, conf, prior);
    select_kernel<<<NB, NT, SMEM_BYTES>>>(out);
}